// round 7
// baseline (speedup 1.0000x reference)
#include <cuda_runtime.h>
#include <cuda_bf16.h>
#include <math.h>
#include <stdint.h>

// ---------------------------------------------------------------------------
// Problem constants
// ---------------------------------------------------------------------------
namespace {
constexpr int cB   = 2;
constexpr int cS   = 2048;
constexpr int cHID = 2048;
constexpr int cNH  = 16;
constexpr int cNKV = 8;
constexpr int cHD  = 128;
constexpr float cEPS   = 1e-6f;
constexpr float cSCALE = 0.08838834764831845f;  // 128^-0.5
constexpr int cM   = cB * cS;        // 4096
constexpr int cNQKV = 4096;          // fused QKV output width (2048+1024+1024)
}

// ---------------------------------------------------------------------------
// Scratch (device globals -- no runtime allocation allowed)
// ---------------------------------------------------------------------------
__device__ float g_ahf [(size_t)cM * cHID];        // tf32-rounded hidden
__device__ float g_qkv [(size_t)cM * cNQKV];       // fused QKV projection out
__device__ float g_att [(size_t)cM * cNH * cHD];   // attn out pre-Wo (tf32-rounded)
__device__ float g_wt  [(size_t)cNQKV * cHID];     // [wq|wk|wv]^T tf32-rounded
__device__ float g_wot [(size_t)cHID * cHID];      // wo^T tf32-rounded
__device__ float g_l   [(size_t)cB * cNH * cS];    // softmax row sums

// bf16 hi/lo planes for attention, head-major layout [b][h][s][d]
__device__ __nv_bfloat16 g_q2hi[(size_t)cB * cNH  * cS * cHD];
__device__ __nv_bfloat16 g_q2lo[(size_t)cB * cNH  * cS * cHD];
__device__ __nv_bfloat16 g_k2hi[(size_t)cB * cNKV * cS * cHD];
__device__ __nv_bfloat16 g_k2lo[(size_t)cB * cNKV * cS * cHD];
__device__ __nv_bfloat16 g_v2hi[(size_t)cB * cNKV * cS * cHD];
__device__ __nv_bfloat16 g_v2lo[(size_t)cB * cNKV * cS * cHD];

// ---------------------------------------------------------------------------
// PTX helpers (portable: sm_80+)
// ---------------------------------------------------------------------------
__device__ __forceinline__ uint32_t smem_u32(const void* p) {
    uint32_t a;
    asm("{ .reg .u64 t; cvta.to.shared.u64 t, %1; cvt.u32.u64 %0, t; }"
        : "=r"(a) : "l"(p));
    return a;
}
__device__ __forceinline__ void cp_async16(uint32_t saddr, const void* gaddr) {
    asm volatile("cp.async.cg.shared.global [%0], [%1], 16;"
                 :: "r"(saddr), "l"(gaddr) : "memory");
}
#define CP_COMMIT()  asm volatile("cp.async.commit_group;" ::: "memory")
#define CP_WAIT(N)   asm volatile("cp.async.wait_group %0;" :: "n"(N) : "memory")

__device__ __forceinline__ void ldm_x4(uint32_t* r, uint32_t addr) {
    asm volatile("ldmatrix.sync.aligned.m8n8.x4.shared.b16 {%0,%1,%2,%3}, [%4];"
                 : "=r"(r[0]), "=r"(r[1]), "=r"(r[2]), "=r"(r[3]) : "r"(addr));
}
__device__ __forceinline__ void ldm_x4t(uint32_t* r, uint32_t addr) {
    asm volatile("ldmatrix.sync.aligned.m8n8.x4.trans.shared.b16 {%0,%1,%2,%3}, [%4];"
                 : "=r"(r[0]), "=r"(r[1]), "=r"(r[2]), "=r"(r[3]) : "r"(addr));
}
__device__ __forceinline__ void mma16816(float* d, const uint32_t* a,
                                         const uint32_t* b) {
    asm volatile(
        "mma.sync.aligned.m16n8k16.row.col.f32.bf16.bf16.f32 "
        "{%0,%1,%2,%3}, {%4,%5,%6,%7}, {%8,%9}, {%0,%1,%2,%3};"
        : "+f"(d[0]), "+f"(d[1]), "+f"(d[2]), "+f"(d[3])
        : "r"(a[0]), "r"(a[1]), "r"(a[2]), "r"(a[3]), "r"(b[0]), "r"(b[1]));
}
__device__ __forceinline__ void mma1688_tf32(float* d, const uint32_t* a,
                                             const uint32_t* b) {
    asm volatile(
        "mma.sync.aligned.m16n8k8.row.col.f32.tf32.tf32.f32 "
        "{%0,%1,%2,%3}, {%4,%5,%6,%7}, {%8,%9}, {%0,%1,%2,%3};"
        : "+f"(d[0]), "+f"(d[1]), "+f"(d[2]), "+f"(d[3])
        : "r"(a[0]), "r"(a[1]), "r"(a[2]), "r"(a[3]), "r"(b[0]), "r"(b[1]));
}
__device__ __forceinline__ uint32_t sw128(uint32_t off) {
    return off ^ ((off >> 3) & 0x70);
}
__device__ __forceinline__ uint32_t pack_bf16(float lo, float hi) {
    __nv_bfloat162 h2 = __floats2bfloat162_rn(lo, hi);
    return *reinterpret_cast<uint32_t*>(&h2);
}
__device__ __forceinline__ float tf32r(float x) {
    uint32_t u;
    asm("cvt.rna.tf32.f32 %0, %1;" : "=r"(u) : "f"(x));
    return __uint_as_float(u);
}

// ---------------------------------------------------------------------------
// Prep kernels
// ---------------------------------------------------------------------------
__global__ __launch_bounds__(256) void round_tf32_kernel(
    const float* __restrict__ X, float* __restrict__ Y)
{
    size_t e = ((size_t)blockIdx.x * 256 + threadIdx.x) * 4;
    float4 x = *(const float4*)(X + e);
    x.x = tf32r(x.x); x.y = tf32r(x.y); x.z = tf32r(x.z); x.w = tf32r(x.w);
    *(float4*)(Y + e) = x;
}

__global__ __launch_bounds__(256) void cvt_wT_kernel(
    const float* __restrict__ W, float* __restrict__ Y, int K, int N)
{
    __shared__ float t[32][33];
    int n0 = blockIdx.x * 32;
    int k0 = blockIdx.y * 32;
    int tx = threadIdx.x;
    int ty = threadIdx.y;
#pragma unroll
    for (int i = 0; i < 32; i += 8)
        t[ty + i][tx] = W[(size_t)(k0 + ty + i) * N + n0 + tx];
    __syncthreads();
#pragma unroll
    for (int i = 0; i < 32; i += 8) {
        int n = n0 + ty + i;
        int k = k0 + tx;
        Y[(size_t)n * K + k] = tf32r(t[tx][ty + i]);
    }
}

// ---------------------------------------------------------------------------
// TF32 HMMA GEMM: C[M,N] = A[M,K] @ B[N,K]^T (row-major fp32, tf32-prerounded)
// CTA tile 128x256, BK=32, 3-stage cp.async, SW128.
// 8 warps in a 2(M) x 4(N) grid, warp tile 64x64, mma.sync m16n8k8 tf32.
// ---------------------------------------------------------------------------
namespace {
constexpr int GBM = 128, GBN = 256, GBK = 32;       // GBK in fp32 elements
constexpr int NSTAGE = 3;
constexpr int A_BYTES = GBM * GBK * 4;              // 16KB
constexpr int B_BYTES = GBN * GBK * 4;              // 32KB
constexpr int STAGE_BYTES = A_BYTES + B_BYTES;      // 48KB
constexpr int GEMM_SMEM   = NSTAGE * STAGE_BYTES;   // 144KB
}

__device__ __forceinline__ void gemm_load_stage(
    const float* __restrict__ Ag, const float* __restrict__ Bg,
    int K, int it, uint32_t stage_base, int tid)
{
#pragma unroll
    for (int i = 0; i < 4; i++) {
        int idx = tid + (i << 8);
        int row = idx >> 3;
        int c4  = idx & 7;
        uint32_t sw = sw128((uint32_t)(row * 128 + c4 * 16));
        cp_async16(stage_base + sw,
                   Ag + (size_t)row * K + (size_t)it * GBK + c4 * 4);
    }
#pragma unroll
    for (int i = 0; i < 8; i++) {
        int idx = tid + (i << 8);
        int row = idx >> 3;
        int c4  = idx & 7;
        uint32_t sw = sw128((uint32_t)(row * 128 + c4 * 16));
        cp_async16(stage_base + A_BYTES + sw,
                   Bg + (size_t)row * K + (size_t)it * GBK + c4 * 4);
    }
}

__global__ __launch_bounds__(256, 1)
void gemm_tf32_kernel(const float* __restrict__ A,
                      const float* __restrict__ B,
                      float* __restrict__ C, int M, int N, int K)
{
    extern __shared__ char smraw[];
    const uint32_t sbase = smem_u32(smraw);

    const int tid  = threadIdx.x;
    const int wid  = tid >> 5;
    const int lane = tid & 31;
    const int m0 = blockIdx.y * GBM;
    const int n0 = blockIdx.x * GBN;
    const int mw = (wid >> 2) * 64;
    const int nw = (wid & 3) * 64;

    const float* Ag = A + (size_t)m0 * K;
    const float* Bg = B + (size_t)n0 * K;
    const int KITERS = K / GBK;

    float acc[4][8][4];
#pragma unroll
    for (int i = 0; i < 4; i++)
#pragma unroll
        for (int j = 0; j < 8; j++)
#pragma unroll
            for (int r = 0; r < 4; r++) acc[i][j][r] = 0.f;

    const int a_row = lane & 15;
    const int a_cb  = (lane >> 4) * 16;
    const int b_row = (lane & 7) + ((lane >> 4) & 1) * 8;
    const int b_cb  = ((lane >> 3) & 1) * 16;

#pragma unroll
    for (int s = 0; s < NSTAGE - 1; s++) {
        gemm_load_stage(Ag, Bg, K, s, sbase + s * STAGE_BYTES, tid);
        CP_COMMIT();
    }

    for (int it = 0; it < KITERS; ++it) {
        CP_WAIT(NSTAGE - 2);
        __syncthreads();

        int nx = it + NSTAGE - 1;
        if (nx < KITERS)
            gemm_load_stage(Ag, Bg, K, nx,
                            sbase + (nx % NSTAGE) * STAGE_BYTES, tid);
        CP_COMMIT();

        const uint32_t sa = sbase + (it % NSTAGE) * STAGE_BYTES;
        const uint32_t sb = sa + A_BYTES;

#pragma unroll
        for (int ks = 0; ks < 4; ks++) {
            uint32_t af[4][4], bf[4][4];
#pragma unroll
            for (int mi = 0; mi < 4; mi++) {
                uint32_t off = (uint32_t)((mw + 16 * mi + a_row) * 128 +
                                          ks * 32 + a_cb);
                ldm_x4(af[mi], sa + sw128(off));
            }
#pragma unroll
            for (int njp = 0; njp < 4; njp++) {
                uint32_t off = (uint32_t)((nw + 16 * njp + b_row) * 128 +
                                          ks * 32 + b_cb);
                ldm_x4(bf[njp], sb + sw128(off));
            }
#pragma unroll
            for (int mi = 0; mi < 4; mi++)
#pragma unroll
                for (int njp = 0; njp < 4; njp++) {
                    mma1688_tf32(acc[mi][2 * njp],     af[mi], bf[njp]);
                    mma1688_tf32(acc[mi][2 * njp + 1], af[mi], bf[njp] + 2);
                }
        }
    }

    const int g = lane >> 2;
    const int t = lane & 3;
#pragma unroll
    for (int mi = 0; mi < 4; mi++) {
#pragma unroll
        for (int nj = 0; nj < 8; nj++) {
            int r0 = m0 + mw + 16 * mi + g;
            int cc = n0 + nw + 8 * nj + t * 2;
            *(float2*)(C + (size_t)r0 * N + cc) =
                make_float2(acc[mi][nj][0], acc[mi][nj][1]);
            *(float2*)(C + (size_t)(r0 + 8) * N + cc) =
                make_float2(acc[mi][nj][2], acc[mi][nj][3]);
        }
    }
}

// ---------------------------------------------------------------------------
// RMSNorm + RoPE + hi/lo bf16 split, reading fused QKV buffer.
// ---------------------------------------------------------------------------
__global__ __launch_bounds__(128) void norm_rope_split_kernel(
    const float* __restrict__ cosp, const float* __restrict__ sinp,
    const float* __restrict__ qw,   const float* __restrict__ kw)
{
    const int slot = blockIdx.x & 31;
    const int bs   = blockIdx.x >> 5;
    const int d    = threadIdx.x;
    const int b    = bs >> 11;
    const int s    = bs & 2047;

    float val;
    __nv_bfloat16 *dhi, *dlo;

    if (slot < 24) {
        const float* src;
        const float* w;
        size_t dst;
        if (slot < 16) {
            src = g_qkv + (size_t)bs * cNQKV + slot * cHD;
            w = qw;
            dst = ((size_t)(b * cNH + slot) * cS + s) * cHD;
            dhi = g_q2hi + dst; dlo = g_q2lo + dst;
        } else {
            src = g_qkv + (size_t)bs * cNQKV + 2048 + (slot - 16) * cHD;
            w = kw;
            dst = ((size_t)(b * cNKV + (slot - 16)) * cS + s) * cHD;
            dhi = g_k2hi + dst; dlo = g_k2lo + dst;
        }
        float x = src[d];
        float v = x * x;
#pragma unroll
        for (int o = 16; o; o >>= 1) v += __shfl_xor_sync(0xffffffffu, v, o);
        __shared__ float wsum[4];
        if ((d & 31) == 0) wsum[d >> 5] = v;
        __syncthreads();
        float var = (wsum[0] + wsum[1] + wsum[2] + wsum[3]) * (1.f / cHD);
        float rs  = rsqrtf(var + cEPS);
        float xn  = x * rs * w[d];

        __shared__ float buf[cHD];
        buf[d] = xn;
        __syncthreads();
        float other = (d < cHD / 2) ? -buf[d + cHD / 2] : buf[d - cHD / 2];
        float cv = cosp[(size_t)bs * cHD + d];
        float sv = sinp[(size_t)bs * cHD + d];
        val = xn * cv + other * sv;
    } else {
        const float* src = g_qkv + (size_t)bs * cNQKV + 3072 + (slot - 24) * cHD;
        size_t dst = ((size_t)(b * cNKV + (slot - 24)) * cS + s) * cHD;
        dhi = g_v2hi + dst; dlo = g_v2lo + dst;
        val = src[d];
    }

    __nv_bfloat16 hi = __float2bfloat16(val);
    __nv_bfloat16 lo = __float2bfloat16(val - __bfloat162float(hi));
    dhi[d] = hi;
    dlo[d] = lo;
}

// ---------------------------------------------------------------------------
// Single-pass MMA attention (bf16 3-term hi/lo).
// Grid: (B*NKV, 32 q-tiles). Heavy-first: qt descends with blockIdx.y so the
// longest (most k-tiles) CTAs launch in wave 1 (LPT scheduling).
// ---------------------------------------------------------------------------
namespace {
constexpr int ARS = 136;
constexpr int ATB = 64 * ARS * 2;
constexpr int ATTN_SMEM = 12 * ATB;
}

__global__ __launch_bounds__(256, 1)
void attn_mma_kernel(const __nv_bfloat16* __restrict__ qhi_g,
                     const __nv_bfloat16* __restrict__ qlo_g,
                     const __nv_bfloat16* __restrict__ khi_g,
                     const __nv_bfloat16* __restrict__ klo_g,
                     const __nv_bfloat16* __restrict__ vhi_g,
                     const __nv_bfloat16* __restrict__ vlo_g,
                     float* __restrict__ wout,
                     float* __restrict__ lsum,
                     float* __restrict__ outp,
                     int write_w)
{
    extern __shared__ char smraw[];
    const uint32_t uQ  = smem_u32(smraw);
    const uint32_t uKV = uQ + 4 * ATB;

    const int tid  = threadIdx.x;
    const int wid  = tid >> 5;
    const int lane = tid & 31;
    const int qt  = gridDim.y - 1 - blockIdx.y;    // heavy-first
    const int bkv = blockIdx.x;
    const int b   = bkv >> 3;
    const int kvh = bkv & 7;
    const int hs  = wid >> 2;
    const int h   = kvh * 2 + hs;
    const int wr  = (wid & 3) * 16;
    const int q0  = qt * 64;
    const int g   = lane >> 2;
    const int t   = lane & 3;

    {
        const size_t qrow = ((size_t)(b * cNH + kvh * 2) * cS + q0) * cHD;
        const int row = (tid >> 4);
        const int c   = tid & 15;
#pragma unroll
        for (int i = 0; i < 16; i++) {
            const int tile = i >> 2;
            const int rr = (i & 3) * 16 + row;
            const __nv_bfloat16* base = (tile & 1) ? qlo_g : qhi_g;
            const __nv_bfloat16* src = base + qrow +
                (size_t)(tile >> 1) * cS * cHD + (size_t)rr * cHD + c * 8;
            cp_async16(uQ + tile * ATB + rr * 272 + c * 16, src);
        }
    }
    CP_COMMIT();

    const size_t kvrow0 = ((size_t)(b * cNKV + kvh) * cS) * cHD;
    {
        const int row = (tid >> 4);
        const int c   = tid & 15;
#pragma unroll
        for (int i = 0; i < 16; i++) {
            const int tile = i >> 2;
            const int rr = (i & 3) * 16 + row;
            const __nv_bfloat16* base =
                (tile == 0) ? khi_g : (tile == 1) ? klo_g :
                (tile == 2) ? vhi_g : vlo_g;
            cp_async16(uKV + tile * ATB + rr * 272 + c * 16,
                       base + kvrow0 + (size_t)rr * cHD + c * 8);
        }
    }
    CP_COMMIT();

    const uint32_t qoff = (uint32_t)((wr + (lane & 15)) * 272 + (lane >> 4) * 16);
    const uint32_t koff = (uint32_t)(((lane & 7) + ((lane >> 4) & 1) * 8) * 272 +
                                     ((lane >> 3) & 1) * 16);
    const uint32_t voff = (uint32_t)(((lane & 7) + ((lane >> 3) & 1) * 8) * 272 +
                                     (lane >> 4) * 16);
    const uint32_t uQh = uQ + hs * 2 * ATB;
    const uint32_t uQl = uQh + ATB;

    float oacc[16][4];
#pragma unroll
    for (int i = 0; i < 16; i++)
#pragma unroll
        for (int r = 0; r < 4; r++) oacc[i][r] = 0.f;
    float l0 = 0.f, l1 = 0.f;

    for (int kt = 0; kt <= qt; kt++) {
        if (kt < qt) {
            const int st = (kt + 1) & 1;
            const size_t kvrow = kvrow0 + (size_t)((kt + 1) * 64) * cHD;
            const int row = (tid >> 4);
            const int c   = tid & 15;
#pragma unroll
            for (int i = 0; i < 16; i++) {
                const int tile = i >> 2;
                const int rr = (i & 3) * 16 + row;
                const __nv_bfloat16* base =
                    (tile == 0) ? khi_g : (tile == 1) ? klo_g :
                    (tile == 2) ? vhi_g : vlo_g;
                cp_async16(uKV + st * 4 * ATB + tile * ATB + rr * 272 + c * 16,
                           base + kvrow + (size_t)rr * cHD + c * 8);
            }
            CP_COMMIT();
            CP_WAIT(1);
        } else {
            CP_WAIT(0);
        }
        __syncthreads();

        const uint32_t ukv  = uKV + (kt & 1) * 4 * ATB;
        const uint32_t ukhi = ukv;
        const uint32_t uklo = ukv + ATB;
        const uint32_t uvhi = ukv + 2 * ATB;
        const uint32_t uvlo = ukv + 3 * ATB;

        float sacc[8][4];
#pragma unroll
        for (int i = 0; i < 8; i++)
#pragma unroll
            for (int r = 0; r < 4; r++) sacc[i][r] = 0.f;

#pragma unroll
        for (int kk = 0; kk < 8; kk++) {
            uint32_t qh[4], ql[4];
            ldm_x4(qh, uQh + qoff + kk * 32);
            ldm_x4(ql, uQl + qoff + kk * 32);
#pragma unroll
            for (int njp = 0; njp < 4; njp++) {
                uint32_t kb[4];
                ldm_x4(kb, ukhi + njp * (16 * 272) + koff + kk * 32);
                mma16816(sacc[2 * njp],     qh, kb);
                mma16816(sacc[2 * njp + 1], qh, kb + 2);
                mma16816(sacc[2 * njp],     ql, kb);
                mma16816(sacc[2 * njp + 1], ql, kb + 2);
            }
#pragma unroll
            for (int njp = 0; njp < 4; njp++) {
                uint32_t kb[4];
                ldm_x4(kb, uklo + njp * (16 * 272) + koff + kk * 32);
                mma16816(sacc[2 * njp],     qh, kb);
                mma16816(sacc[2 * njp + 1], qh, kb + 2);
            }
        }

        const bool diag = (kt == qt);
        uint32_t ahi[4][4], alo[4][4];
#pragma unroll
        for (int nj = 0; nj < 8; nj++) {
            float p0 = __expf(sacc[nj][0] * cSCALE);
            float p1 = __expf(sacc[nj][1] * cSCALE);
            float p2 = __expf(sacc[nj][2] * cSCALE);
            float p3 = __expf(sacc[nj][3] * cSCALE);
            if (diag) {
                const int cbase = nj * 8 + 2 * t;
                const int rlo = wr + g, rhi = wr + 8 + g;
                if (cbase     > rlo) p0 = 0.f;
                if (cbase + 1 > rlo) p1 = 0.f;
                if (cbase     > rhi) p2 = 0.f;
                if (cbase + 1 > rhi) p3 = 0.f;
            }
            l0 += p0 + p1;
            l1 += p2 + p3;
            if (write_w) {
                float* wp = wout + ((size_t)(b * cNH + h) * cS + q0 + wr + g) * cS
                            + kt * 64 + nj * 8 + 2 * t;
                *(float2*)wp = make_float2(p0, p1);
                *(float2*)(wp + 8 * (size_t)cS) = make_float2(p2, p3);
            }
            float h0 = __bfloat162float(__float2bfloat16(p0));
            float h1 = __bfloat162float(__float2bfloat16(p1));
            float h2 = __bfloat162float(__float2bfloat16(p2));
            float h3 = __bfloat162float(__float2bfloat16(p3));
            const int kkB = nj >> 1;
            const int sub = (nj & 1) * 2;
            ahi[kkB][sub]     = pack_bf16(h0, h1);
            ahi[kkB][sub + 1] = pack_bf16(h2, h3);
            alo[kkB][sub]     = pack_bf16(p0 - h0, p1 - h1);
            alo[kkB][sub + 1] = pack_bf16(p2 - h2, p3 - h3);
        }

#pragma unroll
        for (int kk = 0; kk < 4; kk++) {
#pragma unroll
            for (int ndp = 0; ndp < 8; ndp++) {
                uint32_t vb[4];
                ldm_x4t(vb, uvhi + kk * (16 * 272) + ndp * 32 + voff);
                mma16816(oacc[2 * ndp],     ahi[kk], vb);
                mma16816(oacc[2 * ndp + 1], ahi[kk], vb + 2);
                mma16816(oacc[2 * ndp],     alo[kk], vb);
                mma16816(oacc[2 * ndp + 1], alo[kk], vb + 2);
            }
#pragma unroll
            for (int ndp = 0; ndp < 8; ndp++) {
                uint32_t vb[4];
                ldm_x4t(vb, uvlo + kk * (16 * 272) + ndp * 32 + voff);
                mma16816(oacc[2 * ndp],     ahi[kk], vb);
                mma16816(oacc[2 * ndp + 1], ahi[kk], vb + 2);
            }
        }
        __syncthreads();
    }

    l0 += __shfl_xor_sync(0xffffffffu, l0, 1);
    l0 += __shfl_xor_sync(0xffffffffu, l0, 2);
    l1 += __shfl_xor_sync(0xffffffffu, l1, 1);
    l1 += __shfl_xor_sync(0xffffffffu, l1, 2);
    const float inv0 = 1.f / l0;
    const float inv1 = 1.f / l1;

    if (write_w && t == 0) {
        lsum[(size_t)(b * cNH + h) * cS + q0 + wr + g]     = l0;
        lsum[(size_t)(b * cNH + h) * cS + q0 + wr + 8 + g] = l1;
    }

#pragma unroll
    for (int nd = 0; nd < 16; nd++) {
        const int col = nd * 8 + 2 * t;
        float* o0 = outp + ((size_t)(b * cS + q0 + wr + g) * cNH + h) * cHD + col;
        float* o1 = outp + ((size_t)(b * cS + q0 + wr + 8 + g) * cNH + h) * cHD + col;
        *(float2*)o0 = make_float2(tf32r(oacc[nd][0] * inv0),
                                   tf32r(oacc[nd][1] * inv0));
        *(float2*)o1 = make_float2(tf32r(oacc[nd][2] * inv1),
                                   tf32r(oacc[nd][3] * inv1));
    }
}

// ---------------------------------------------------------------------------
// Normalize weights rows by 1/l; zero the never-written upper triangle.
// ---------------------------------------------------------------------------
__global__ __launch_bounds__(256) void norm_weights_kernel(
    float* __restrict__ w, const float* __restrict__ lsum)
{
    const int row = blockIdx.x;
    const int q   = row & (cS - 1);
    const int valid = ((q >> 6) + 1) << 6;
    const float inv = 1.f / lsum[row];
    float* wr = w + (size_t)row * cS;
    const int tid = threadIdx.x;
#pragma unroll
    for (int i = 0; i < 2; i++) {
        int c = (tid + i * 256) * 4;
        if (c < valid) {
            float4 v = *(float4*)(wr + c);
            v.x *= inv; v.y *= inv; v.z *= inv; v.w *= inv;
            *(float4*)(wr + c) = v;
        } else {
            *(float4*)(wr + c) = make_float4(0.f, 0.f, 0.f, 0.f);
        }
    }
}

// ---------------------------------------------------------------------------
// Launch (two-stream fork/join graph)
// ---------------------------------------------------------------------------
extern "C" void kernel_launch(void* const* d_in, const int* in_sizes, int n_in,
                              void* d_out, int out_size)
{
    const float* hidden = (const float*)d_in[0];
    const float* cosp   = (const float*)d_in[1];
    const float* sinp   = (const float*)d_in[2];
    const float* wq  = (const float*)d_in[4];
    const float* wk  = (const float*)d_in[5];
    const float* wv  = (const float*)d_in[6];
    const float* wo  = (const float*)d_in[7];
    const float* qnw = (const float*)d_in[8];
    const float* knw = (const float*)d_in[9];

    float* out = (float*)d_out;
    const size_t n_attn = (size_t)cM * cHID;
    const size_t n_w    = (size_t)cB * cNH * cS * cS;
    const int write_w   = ((size_t)out_size >= n_attn + n_w) ? 1 : 0;
    float* weights = out + n_attn;

    float *pahf, *pqkv, *pa, *pwt, *pwot, *pl;
    cudaGetSymbolAddress((void**)&pahf, g_ahf);
    cudaGetSymbolAddress((void**)&pqkv, g_qkv);
    cudaGetSymbolAddress((void**)&pa,   g_att);
    cudaGetSymbolAddress((void**)&pwt,  g_wt);
    cudaGetSymbolAddress((void**)&pwot, g_wot);
    cudaGetSymbolAddress((void**)&pl,   g_l);
    __nv_bfloat16 *pqh, *pql, *pkh, *pklo, *pvh, *pvlo;
    cudaGetSymbolAddress((void**)&pqh,  g_q2hi);
    cudaGetSymbolAddress((void**)&pql,  g_q2lo);
    cudaGetSymbolAddress((void**)&pkh,  g_k2hi);
    cudaGetSymbolAddress((void**)&pklo, g_k2lo);
    cudaGetSymbolAddress((void**)&pvh,  g_v2hi);
    cudaGetSymbolAddress((void**)&pvlo, g_v2lo);

    static cudaStream_t s1 = nullptr;
    static cudaEvent_t evF1, evJ1, evF2, evJ2;
    if (!s1) {
        cudaStreamCreateWithFlags(&s1, cudaStreamNonBlocking);
        cudaEventCreateWithFlags(&evF1, cudaEventDisableTiming);
        cudaEventCreateWithFlags(&evJ1, cudaEventDisableTiming);
        cudaEventCreateWithFlags(&evF2, cudaEventDisableTiming);
        cudaEventCreateWithFlags(&evJ2, cudaEventDisableTiming);
        cudaFuncSetAttribute(gemm_tf32_kernel,
                             cudaFuncAttributeMaxDynamicSharedMemorySize, GEMM_SMEM);
        cudaFuncSetAttribute(attn_mma_kernel,
                             cudaFuncAttributeMaxDynamicSharedMemorySize, ATTN_SMEM);
    }

    // ---- fork 1: weight transposes on s1, hidden rounding on default ----
    cudaEventRecord(evF1, 0);
    cudaStreamWaitEvent(s1, evF1, 0);
    cvt_wT_kernel<<<dim3(2048 / 32, 2048 / 32), dim3(32, 8), 0, s1>>>(
        wq, pwt, cHID, 2048);
    cvt_wT_kernel<<<dim3(1024 / 32, 2048 / 32), dim3(32, 8), 0, s1>>>(
        wk, pwt + (size_t)2048 * cHID, cHID, 1024);
    cvt_wT_kernel<<<dim3(1024 / 32, 2048 / 32), dim3(32, 8), 0, s1>>>(
        wv, pwt + (size_t)3072 * cHID, cHID, 1024);
    cvt_wT_kernel<<<dim3(2048 / 32, 2048 / 32), dim3(32, 8), 0, s1>>>(
        wo, pwot, cHID, 2048);
    cudaEventRecord(evJ1, s1);

    round_tf32_kernel<<<(cM * cHID / 4) / 256, 256>>>(hidden, pahf);
    cudaStreamWaitEvent(0, evJ1, 0);          // join: QKV GEMM needs pwt

    // ---- serial spine ----
    gemm_tf32_kernel<<<dim3(cNQKV / GBN, cM / GBM), 256, GEMM_SMEM>>>(
        pahf, pwt, pqkv, cM, cNQKV, cHID);

    norm_rope_split_kernel<<<cM * 32, 128>>>(cosp, sinp, qnw, knw);

    attn_mma_kernel<<<dim3(cB * cNKV, cS / 64), 256, ATTN_SMEM>>>(
        pqh, pql, pkh, pklo, pvh, pvlo, weights, pl, pa, write_w);

    // ---- fork 2: norm_weights (DRAM-bound) on s1 ∥ Wo GEMM (tensor-bound) ----
    cudaEventRecord(evF2, 0);
    cudaStreamWaitEvent(s1, evF2, 0);
    if (write_w)
        norm_weights_kernel<<<cB * cNH * cS, 256, 0, s1>>>(weights, pl);
    cudaEventRecord(evJ2, s1);

    gemm_tf32_kernel<<<dim3(cHID / GBN, cM / GBM), 256, GEMM_SMEM>>>(
        pa, pwot, out, cM, cHID, cHID);
    cudaStreamWaitEvent(0, evJ2, 0);          // join both branches
}

// round 8
// speedup vs baseline: 1.4110x; 1.4110x over previous
#include <cuda_runtime.h>
#include <cuda_bf16.h>
#include <math.h>
#include <stdint.h>

// ---------------------------------------------------------------------------
// Problem constants
// ---------------------------------------------------------------------------
namespace {
constexpr int cB   = 2;
constexpr int cS   = 2048;
constexpr int cHID = 2048;
constexpr int cNH  = 16;
constexpr int cNKV = 8;
constexpr int cHD  = 128;
constexpr float cEPS   = 1e-6f;
constexpr float cSCALE = 0.08838834764831845f;  // 128^-0.5
constexpr int cM   = cB * cS;        // 4096
constexpr int cNQKV = 4096;          // fused QKV output width (2048+1024+1024)
}

// ---------------------------------------------------------------------------
// Scratch (device globals -- no runtime allocation allowed)
// ---------------------------------------------------------------------------
__device__ float g_ahf [(size_t)cM * cHID];        // tf32-rounded hidden
__device__ float g_qkv [(size_t)cM * cNQKV];       // fused QKV projection out
__device__ float g_att [(size_t)cM * cNH * cHD];   // attn out pre-Wo (tf32-rounded)
__device__ float g_wt  [(size_t)cNQKV * cHID];     // [wq|wk|wv]^T tf32-rounded
__device__ float g_wot [(size_t)cHID * cHID];      // wo^T tf32-rounded

// bf16 hi/lo planes for attention, head-major layout [b][h][s][d]
__device__ __nv_bfloat16 g_q2hi[(size_t)cB * cNH  * cS * cHD];
__device__ __nv_bfloat16 g_q2lo[(size_t)cB * cNH  * cS * cHD];
__device__ __nv_bfloat16 g_k2hi[(size_t)cB * cNKV * cS * cHD];
__device__ __nv_bfloat16 g_k2lo[(size_t)cB * cNKV * cS * cHD];
__device__ __nv_bfloat16 g_v2hi[(size_t)cB * cNKV * cS * cHD];
__device__ __nv_bfloat16 g_v2lo[(size_t)cB * cNKV * cS * cHD];

// ---------------------------------------------------------------------------
// PTX helpers (portable: sm_80+)
// ---------------------------------------------------------------------------
__device__ __forceinline__ uint32_t smem_u32(const void* p) {
    uint32_t a;
    asm("{ .reg .u64 t; cvta.to.shared.u64 t, %1; cvt.u32.u64 %0, t; }"
        : "=r"(a) : "l"(p));
    return a;
}
__device__ __forceinline__ void cp_async16(uint32_t saddr, const void* gaddr) {
    asm volatile("cp.async.cg.shared.global [%0], [%1], 16;"
                 :: "r"(saddr), "l"(gaddr) : "memory");
}
#define CP_COMMIT()  asm volatile("cp.async.commit_group;" ::: "memory")
#define CP_WAIT(N)   asm volatile("cp.async.wait_group %0;" :: "n"(N) : "memory")

__device__ __forceinline__ void ldm_x4(uint32_t* r, uint32_t addr) {
    asm volatile("ldmatrix.sync.aligned.m8n8.x4.shared.b16 {%0,%1,%2,%3}, [%4];"
                 : "=r"(r[0]), "=r"(r[1]), "=r"(r[2]), "=r"(r[3]) : "r"(addr));
}
__device__ __forceinline__ void ldm_x4t(uint32_t* r, uint32_t addr) {
    asm volatile("ldmatrix.sync.aligned.m8n8.x4.trans.shared.b16 {%0,%1,%2,%3}, [%4];"
                 : "=r"(r[0]), "=r"(r[1]), "=r"(r[2]), "=r"(r[3]) : "r"(addr));
}
__device__ __forceinline__ void mma16816(float* d, const uint32_t* a,
                                         const uint32_t* b) {
    asm volatile(
        "mma.sync.aligned.m16n8k16.row.col.f32.bf16.bf16.f32 "
        "{%0,%1,%2,%3}, {%4,%5,%6,%7}, {%8,%9}, {%0,%1,%2,%3};"
        : "+f"(d[0]), "+f"(d[1]), "+f"(d[2]), "+f"(d[3])
        : "r"(a[0]), "r"(a[1]), "r"(a[2]), "r"(a[3]), "r"(b[0]), "r"(b[1]));
}
__device__ __forceinline__ void mma1688_tf32(float* d, const uint32_t* a,
                                             const uint32_t* b) {
    asm volatile(
        "mma.sync.aligned.m16n8k8.row.col.f32.tf32.tf32.f32 "
        "{%0,%1,%2,%3}, {%4,%5,%6,%7}, {%8,%9}, {%0,%1,%2,%3};"
        : "+f"(d[0]), "+f"(d[1]), "+f"(d[2]), "+f"(d[3])
        : "r"(a[0]), "r"(a[1]), "r"(a[2]), "r"(a[3]), "r"(b[0]), "r"(b[1]));
}
__device__ __forceinline__ uint32_t sw128(uint32_t off) {
    return off ^ ((off >> 3) & 0x70);
}
__device__ __forceinline__ uint32_t pack_bf16(float lo, float hi) {
    __nv_bfloat162 h2 = __floats2bfloat162_rn(lo, hi);
    return *reinterpret_cast<uint32_t*>(&h2);
}
__device__ __forceinline__ float tf32r(float x) {
    uint32_t u;
    asm("cvt.rna.tf32.f32 %0, %1;" : "=r"(u) : "f"(x));
    return __uint_as_float(u);
}

// ---------------------------------------------------------------------------
// Prep kernels
// ---------------------------------------------------------------------------
__global__ __launch_bounds__(256) void round_tf32_kernel(
    const float* __restrict__ X, float* __restrict__ Y)
{
    size_t e = ((size_t)blockIdx.x * 256 + threadIdx.x) * 4;
    float4 x = *(const float4*)(X + e);
    x.x = tf32r(x.x); x.y = tf32r(x.y); x.z = tf32r(x.z); x.w = tf32r(x.w);
    *(float4*)(Y + e) = x;
}

__global__ __launch_bounds__(256) void cvt_wT_kernel(
    const float* __restrict__ W, float* __restrict__ Y, int K, int N)
{
    __shared__ float t[32][33];
    int n0 = blockIdx.x * 32;
    int k0 = blockIdx.y * 32;
    int tx = threadIdx.x;
    int ty = threadIdx.y;
#pragma unroll
    for (int i = 0; i < 32; i += 8)
        t[ty + i][tx] = W[(size_t)(k0 + ty + i) * N + n0 + tx];
    __syncthreads();
#pragma unroll
    for (int i = 0; i < 32; i += 8) {
        int n = n0 + ty + i;
        int k = k0 + tx;
        Y[(size_t)n * K + k] = tf32r(t[tx][ty + i]);
    }
}

// ---------------------------------------------------------------------------
// TF32 HMMA GEMM: C[M,N] = A[M,K] @ B[N,K]^T (row-major fp32, tf32-prerounded)
// CTA tile 128x256, BK=32, 3-stage cp.async, SW128.
// 8 warps in a 2(M) x 4(N) grid, warp tile 64x64, mma.sync m16n8k8 tf32.
// ---------------------------------------------------------------------------
namespace {
constexpr int GBM = 128, GBN = 256, GBK = 32;       // GBK in fp32 elements
constexpr int NSTAGE = 3;
constexpr int A_BYTES = GBM * GBK * 4;              // 16KB
constexpr int B_BYTES = GBN * GBK * 4;              // 32KB
constexpr int STAGE_BYTES = A_BYTES + B_BYTES;      // 48KB
constexpr int GEMM_SMEM   = NSTAGE * STAGE_BYTES;   // 144KB
}

__device__ __forceinline__ void gemm_load_stage(
    const float* __restrict__ Ag, const float* __restrict__ Bg,
    int K, int it, uint32_t stage_base, int tid)
{
#pragma unroll
    for (int i = 0; i < 4; i++) {
        int idx = tid + (i << 8);
        int row = idx >> 3;
        int c4  = idx & 7;
        uint32_t sw = sw128((uint32_t)(row * 128 + c4 * 16));
        cp_async16(stage_base + sw,
                   Ag + (size_t)row * K + (size_t)it * GBK + c4 * 4);
    }
#pragma unroll
    for (int i = 0; i < 8; i++) {
        int idx = tid + (i << 8);
        int row = idx >> 3;
        int c4  = idx & 7;
        uint32_t sw = sw128((uint32_t)(row * 128 + c4 * 16));
        cp_async16(stage_base + A_BYTES + sw,
                   Bg + (size_t)row * K + (size_t)it * GBK + c4 * 4);
    }
}

__global__ __launch_bounds__(256, 1)
void gemm_tf32_kernel(const float* __restrict__ A,
                      const float* __restrict__ B,
                      float* __restrict__ C, int M, int N, int K)
{
    extern __shared__ char smraw[];
    const uint32_t sbase = smem_u32(smraw);

    const int tid  = threadIdx.x;
    const int wid  = tid >> 5;
    const int lane = tid & 31;
    const int m0 = blockIdx.y * GBM;
    const int n0 = blockIdx.x * GBN;
    const int mw = (wid >> 2) * 64;
    const int nw = (wid & 3) * 64;

    const float* Ag = A + (size_t)m0 * K;
    const float* Bg = B + (size_t)n0 * K;
    const int KITERS = K / GBK;

    float acc[4][8][4];
#pragma unroll
    for (int i = 0; i < 4; i++)
#pragma unroll
        for (int j = 0; j < 8; j++)
#pragma unroll
            for (int r = 0; r < 4; r++) acc[i][j][r] = 0.f;

    const int a_row = lane & 15;
    const int a_cb  = (lane >> 4) * 16;
    const int b_row = (lane & 7) + ((lane >> 4) & 1) * 8;
    const int b_cb  = ((lane >> 3) & 1) * 16;

#pragma unroll
    for (int s = 0; s < NSTAGE - 1; s++) {
        gemm_load_stage(Ag, Bg, K, s, sbase + s * STAGE_BYTES, tid);
        CP_COMMIT();
    }

    for (int it = 0; it < KITERS; ++it) {
        CP_WAIT(NSTAGE - 2);
        __syncthreads();

        int nx = it + NSTAGE - 1;
        if (nx < KITERS)
            gemm_load_stage(Ag, Bg, K, nx,
                            sbase + (nx % NSTAGE) * STAGE_BYTES, tid);
        CP_COMMIT();

        const uint32_t sa = sbase + (it % NSTAGE) * STAGE_BYTES;
        const uint32_t sb = sa + A_BYTES;

#pragma unroll
        for (int ks = 0; ks < 4; ks++) {
            uint32_t af[4][4], bf[4][4];
#pragma unroll
            for (int mi = 0; mi < 4; mi++) {
                uint32_t off = (uint32_t)((mw + 16 * mi + a_row) * 128 +
                                          ks * 32 + a_cb);
                ldm_x4(af[mi], sa + sw128(off));
            }
#pragma unroll
            for (int njp = 0; njp < 4; njp++) {
                uint32_t off = (uint32_t)((nw + 16 * njp + b_row) * 128 +
                                          ks * 32 + b_cb);
                ldm_x4(bf[njp], sb + sw128(off));
            }
#pragma unroll
            for (int mi = 0; mi < 4; mi++)
#pragma unroll
                for (int njp = 0; njp < 4; njp++) {
                    mma1688_tf32(acc[mi][2 * njp],     af[mi], bf[njp]);
                    mma1688_tf32(acc[mi][2 * njp + 1], af[mi], bf[njp] + 2);
                }
        }
    }

    const int g = lane >> 2;
    const int t = lane & 3;
#pragma unroll
    for (int mi = 0; mi < 4; mi++) {
#pragma unroll
        for (int nj = 0; nj < 8; nj++) {
            int r0 = m0 + mw + 16 * mi + g;
            int cc = n0 + nw + 8 * nj + t * 2;
            *(float2*)(C + (size_t)r0 * N + cc) =
                make_float2(acc[mi][nj][0], acc[mi][nj][1]);
            *(float2*)(C + (size_t)(r0 + 8) * N + cc) =
                make_float2(acc[mi][nj][2], acc[mi][nj][3]);
        }
    }
}

// ---------------------------------------------------------------------------
// RMSNorm + RoPE + hi/lo bf16 split, reading fused QKV buffer.
// ---------------------------------------------------------------------------
__global__ __launch_bounds__(128) void norm_rope_split_kernel(
    const float* __restrict__ cosp, const float* __restrict__ sinp,
    const float* __restrict__ qw,   const float* __restrict__ kw)
{
    const int slot = blockIdx.x & 31;
    const int bs   = blockIdx.x >> 5;
    const int d    = threadIdx.x;
    const int b    = bs >> 11;
    const int s    = bs & 2047;

    float val;
    __nv_bfloat16 *dhi, *dlo;

    if (slot < 24) {
        const float* src;
        const float* w;
        size_t dst;
        if (slot < 16) {
            src = g_qkv + (size_t)bs * cNQKV + slot * cHD;
            w = qw;
            dst = ((size_t)(b * cNH + slot) * cS + s) * cHD;
            dhi = g_q2hi + dst; dlo = g_q2lo + dst;
        } else {
            src = g_qkv + (size_t)bs * cNQKV + 2048 + (slot - 16) * cHD;
            w = kw;
            dst = ((size_t)(b * cNKV + (slot - 16)) * cS + s) * cHD;
            dhi = g_k2hi + dst; dlo = g_k2lo + dst;
        }
        float x = src[d];
        float v = x * x;
#pragma unroll
        for (int o = 16; o; o >>= 1) v += __shfl_xor_sync(0xffffffffu, v, o);
        __shared__ float wsum[4];
        if ((d & 31) == 0) wsum[d >> 5] = v;
        __syncthreads();
        float var = (wsum[0] + wsum[1] + wsum[2] + wsum[3]) * (1.f / cHD);
        float rs  = rsqrtf(var + cEPS);
        float xn  = x * rs * w[d];

        __shared__ float buf[cHD];
        buf[d] = xn;
        __syncthreads();
        float other = (d < cHD / 2) ? -buf[d + cHD / 2] : buf[d - cHD / 2];
        float cv = cosp[(size_t)bs * cHD + d];
        float sv = sinp[(size_t)bs * cHD + d];
        val = xn * cv + other * sv;
    } else {
        const float* src = g_qkv + (size_t)bs * cNQKV + 3072 + (slot - 24) * cHD;
        size_t dst = ((size_t)(b * cNKV + (slot - 24)) * cS + s) * cHD;
        dhi = g_v2hi + dst; dlo = g_v2lo + dst;
        val = src[d];
    }

    __nv_bfloat16 hi = __float2bfloat16(val);
    __nv_bfloat16 lo = __float2bfloat16(val - __bfloat162float(hi));
    dhi[d] = hi;
    dlo[d] = lo;
}

// ---------------------------------------------------------------------------
// Single-pass MMA attention (bf16 3-term hi/lo) with FUSED weight
// normalization + upper-triangle zero-fill (each thread rescales exactly the
// p-values it wrote; each CTA zero-fills its own rows' tail).
// Grid: (B*NKV, 32 q-tiles), heavy-first (LPT) raster on qt.
// ---------------------------------------------------------------------------
namespace {
constexpr int ARS = 136;
constexpr int ATB = 64 * ARS * 2;
constexpr int ATTN_SMEM = 12 * ATB;
}

__global__ __launch_bounds__(256, 1)
void attn_mma_kernel(const __nv_bfloat16* __restrict__ qhi_g,
                     const __nv_bfloat16* __restrict__ qlo_g,
                     const __nv_bfloat16* __restrict__ khi_g,
                     const __nv_bfloat16* __restrict__ klo_g,
                     const __nv_bfloat16* __restrict__ vhi_g,
                     const __nv_bfloat16* __restrict__ vlo_g,
                     float* __restrict__ wout,
                     float* __restrict__ outp,
                     int write_w)
{
    extern __shared__ char smraw[];
    const uint32_t uQ  = smem_u32(smraw);
    const uint32_t uKV = uQ + 4 * ATB;

    const int tid  = threadIdx.x;
    const int wid  = tid >> 5;
    const int lane = tid & 31;
    const int qt  = gridDim.y - 1 - blockIdx.y;    // heavy-first
    const int bkv = blockIdx.x;
    const int b   = bkv >> 3;
    const int kvh = bkv & 7;
    const int hs  = wid >> 2;
    const int h   = kvh * 2 + hs;
    const int wr  = (wid & 3) * 16;
    const int q0  = qt * 64;
    const int g   = lane >> 2;
    const int t   = lane & 3;

    {
        const size_t qrow = ((size_t)(b * cNH + kvh * 2) * cS + q0) * cHD;
        const int row = (tid >> 4);
        const int c   = tid & 15;
#pragma unroll
        for (int i = 0; i < 16; i++) {
            const int tile = i >> 2;
            const int rr = (i & 3) * 16 + row;
            const __nv_bfloat16* base = (tile & 1) ? qlo_g : qhi_g;
            const __nv_bfloat16* src = base + qrow +
                (size_t)(tile >> 1) * cS * cHD + (size_t)rr * cHD + c * 8;
            cp_async16(uQ + tile * ATB + rr * 272 + c * 16, src);
        }
    }
    CP_COMMIT();

    const size_t kvrow0 = ((size_t)(b * cNKV + kvh) * cS) * cHD;
    {
        const int row = (tid >> 4);
        const int c   = tid & 15;
#pragma unroll
        for (int i = 0; i < 16; i++) {
            const int tile = i >> 2;
            const int rr = (i & 3) * 16 + row;
            const __nv_bfloat16* base =
                (tile == 0) ? khi_g : (tile == 1) ? klo_g :
                (tile == 2) ? vhi_g : vlo_g;
            cp_async16(uKV + tile * ATB + rr * 272 + c * 16,
                       base + kvrow0 + (size_t)rr * cHD + c * 8);
        }
    }
    CP_COMMIT();

    const uint32_t qoff = (uint32_t)((wr + (lane & 15)) * 272 + (lane >> 4) * 16);
    const uint32_t koff = (uint32_t)(((lane & 7) + ((lane >> 4) & 1) * 8) * 272 +
                                     ((lane >> 3) & 1) * 16);
    const uint32_t voff = (uint32_t)(((lane & 7) + ((lane >> 3) & 1) * 8) * 272 +
                                     (lane >> 4) * 16);
    const uint32_t uQh = uQ + hs * 2 * ATB;
    const uint32_t uQl = uQh + ATB;

    float oacc[16][4];
#pragma unroll
    for (int i = 0; i < 16; i++)
#pragma unroll
        for (int r = 0; r < 4; r++) oacc[i][r] = 0.f;
    float l0 = 0.f, l1 = 0.f;

    for (int kt = 0; kt <= qt; kt++) {
        if (kt < qt) {
            const int st = (kt + 1) & 1;
            const size_t kvrow = kvrow0 + (size_t)((kt + 1) * 64) * cHD;
            const int row = (tid >> 4);
            const int c   = tid & 15;
#pragma unroll
            for (int i = 0; i < 16; i++) {
                const int tile = i >> 2;
                const int rr = (i & 3) * 16 + row;
                const __nv_bfloat16* base =
                    (tile == 0) ? khi_g : (tile == 1) ? klo_g :
                    (tile == 2) ? vhi_g : vlo_g;
                cp_async16(uKV + st * 4 * ATB + tile * ATB + rr * 272 + c * 16,
                           base + kvrow + (size_t)rr * cHD + c * 8);
            }
            CP_COMMIT();
            CP_WAIT(1);
        } else {
            CP_WAIT(0);
        }
        __syncthreads();

        const uint32_t ukv  = uKV + (kt & 1) * 4 * ATB;
        const uint32_t ukhi = ukv;
        const uint32_t uklo = ukv + ATB;
        const uint32_t uvhi = ukv + 2 * ATB;
        const uint32_t uvlo = ukv + 3 * ATB;

        float sacc[8][4];
#pragma unroll
        for (int i = 0; i < 8; i++)
#pragma unroll
            for (int r = 0; r < 4; r++) sacc[i][r] = 0.f;

#pragma unroll
        for (int kk = 0; kk < 8; kk++) {
            uint32_t qh[4], ql[4];
            ldm_x4(qh, uQh + qoff + kk * 32);
            ldm_x4(ql, uQl + qoff + kk * 32);
#pragma unroll
            for (int njp = 0; njp < 4; njp++) {
                uint32_t kb[4];
                ldm_x4(kb, ukhi + njp * (16 * 272) + koff + kk * 32);
                mma16816(sacc[2 * njp],     qh, kb);
                mma16816(sacc[2 * njp + 1], qh, kb + 2);
                mma16816(sacc[2 * njp],     ql, kb);
                mma16816(sacc[2 * njp + 1], ql, kb + 2);
            }
#pragma unroll
            for (int njp = 0; njp < 4; njp++) {
                uint32_t kb[4];
                ldm_x4(kb, uklo + njp * (16 * 272) + koff + kk * 32);
                mma16816(sacc[2 * njp],     qh, kb);
                mma16816(sacc[2 * njp + 1], qh, kb + 2);
            }
        }

        const bool diag = (kt == qt);
        uint32_t ahi[4][4], alo[4][4];
#pragma unroll
        for (int nj = 0; nj < 8; nj++) {
            float p0 = __expf(sacc[nj][0] * cSCALE);
            float p1 = __expf(sacc[nj][1] * cSCALE);
            float p2 = __expf(sacc[nj][2] * cSCALE);
            float p3 = __expf(sacc[nj][3] * cSCALE);
            if (diag) {
                const int cbase = nj * 8 + 2 * t;
                const int rlo = wr + g, rhi = wr + 8 + g;
                if (cbase     > rlo) p0 = 0.f;
                if (cbase + 1 > rlo) p1 = 0.f;
                if (cbase     > rhi) p2 = 0.f;
                if (cbase + 1 > rhi) p3 = 0.f;
            }
            l0 += p0 + p1;
            l1 += p2 + p3;
            if (write_w) {
                float* wp = wout + ((size_t)(b * cNH + h) * cS + q0 + wr + g) * cS
                            + kt * 64 + nj * 8 + 2 * t;
                *(float2*)wp = make_float2(p0, p1);
                *(float2*)(wp + 8 * (size_t)cS) = make_float2(p2, p3);
            }
            float h0 = __bfloat162float(__float2bfloat16(p0));
            float h1 = __bfloat162float(__float2bfloat16(p1));
            float h2 = __bfloat162float(__float2bfloat16(p2));
            float h3 = __bfloat162float(__float2bfloat16(p3));
            const int kkB = nj >> 1;
            const int sub = (nj & 1) * 2;
            ahi[kkB][sub]     = pack_bf16(h0, h1);
            ahi[kkB][sub + 1] = pack_bf16(h2, h3);
            alo[kkB][sub]     = pack_bf16(p0 - h0, p1 - h1);
            alo[kkB][sub + 1] = pack_bf16(p2 - h2, p3 - h3);
        }

#pragma unroll
        for (int kk = 0; kk < 4; kk++) {
#pragma unroll
            for (int ndp = 0; ndp < 8; ndp++) {
                uint32_t vb[4];
                ldm_x4t(vb, uvhi + kk * (16 * 272) + ndp * 32 + voff);
                mma16816(oacc[2 * ndp],     ahi[kk], vb);
                mma16816(oacc[2 * ndp + 1], ahi[kk], vb + 2);
                mma16816(oacc[2 * ndp],     alo[kk], vb);
                mma16816(oacc[2 * ndp + 1], alo[kk], vb + 2);
            }
#pragma unroll
            for (int ndp = 0; ndp < 8; ndp++) {
                uint32_t vb[4];
                ldm_x4t(vb, uvlo + kk * (16 * 272) + ndp * 32 + voff);
                mma16816(oacc[2 * ndp],     ahi[kk], vb);
                mma16816(oacc[2 * ndp + 1], ahi[kk], vb + 2);
            }
        }
        __syncthreads();
    }

    l0 += __shfl_xor_sync(0xffffffffu, l0, 1);
    l0 += __shfl_xor_sync(0xffffffffu, l0, 2);
    l1 += __shfl_xor_sync(0xffffffffu, l1, 1);
    l1 += __shfl_xor_sync(0xffffffffu, l1, 2);
    const float inv0 = 1.f / l0;
    const float inv1 = 1.f / l1;

    // ---- PV output (normalized, tf32-rounded for the Wo GEMM) ----
#pragma unroll
    for (int nd = 0; nd < 16; nd++) {
        const int col = nd * 8 + 2 * t;
        float* o0 = outp + ((size_t)(b * cS + q0 + wr + g) * cNH + h) * cHD + col;
        float* o1 = outp + ((size_t)(b * cS + q0 + wr + 8 + g) * cNH + h) * cHD + col;
        *(float2*)o0 = make_float2(tf32r(oacc[nd][0] * inv0),
                                   tf32r(oacc[nd][1] * inv0));
        *(float2*)o1 = make_float2(tf32r(oacc[nd][2] * inv1),
                                   tf32r(oacc[nd][3] * inv1));
    }

    // ---- fused weight normalization: rescale exactly what this thread wrote
    if (write_w) {
        const size_t rb0 = ((size_t)(b * cNH + h) * cS + q0 + wr + g) * cS;
        const size_t rb1 = rb0 + 8 * (size_t)cS;
        for (int kt = 0; kt <= qt; kt++) {
#pragma unroll
            for (int nj = 0; nj < 8; nj++) {
                const int cc = kt * 64 + nj * 8 + 2 * t;
                float* w0 = wout + rb0 + cc;
                float2 v0 = *(float2*)w0;
                v0.x *= inv0; v0.y *= inv0;
                *(float2*)w0 = v0;
                float* w1 = wout + rb1 + cc;
                float2 v1 = *(float2*)w1;
                v1.x *= inv1; v1.y *= inv1;
                *(float2*)w1 = v1;
            }
        }
        // ---- zero the upper-triangle tail of this CTA's 128 rows
        const int zc = cS - (q0 + 64);
        if (zc > 0) {
            const int z4 = zc >> 2;
            const int tot = 128 * z4;
            const float4 z = make_float4(0.f, 0.f, 0.f, 0.f);
            for (int i = tid; i < tot; i += 256) {
                const int r  = i / z4;
                const int c4 = i - r * z4;
                const int head = r >> 6;
                const int row  = r & 63;
                float* p = wout +
                    ((size_t)(b * cNH + kvh * 2 + head) * cS + q0 + row) * cS +
                    q0 + 64 + c4 * 4;
                *(float4*)p = z;
            }
        }
    }
}

// ---------------------------------------------------------------------------
// Launch (single stream, R6 ordering)
// ---------------------------------------------------------------------------
extern "C" void kernel_launch(void* const* d_in, const int* in_sizes, int n_in,
                              void* d_out, int out_size)
{
    const float* hidden = (const float*)d_in[0];
    const float* cosp   = (const float*)d_in[1];
    const float* sinp   = (const float*)d_in[2];
    const float* wq  = (const float*)d_in[4];
    const float* wk  = (const float*)d_in[5];
    const float* wv  = (const float*)d_in[6];
    const float* wo  = (const float*)d_in[7];
    const float* qnw = (const float*)d_in[8];
    const float* knw = (const float*)d_in[9];

    float* out = (float*)d_out;
    const size_t n_attn = (size_t)cM * cHID;
    const size_t n_w    = (size_t)cB * cNH * cS * cS;
    const int write_w   = ((size_t)out_size >= n_attn + n_w) ? 1 : 0;
    float* weights = out + n_attn;

    float *pahf, *pqkv, *pa, *pwt, *pwot;
    cudaGetSymbolAddress((void**)&pahf, g_ahf);
    cudaGetSymbolAddress((void**)&pqkv, g_qkv);
    cudaGetSymbolAddress((void**)&pa,   g_att);
    cudaGetSymbolAddress((void**)&pwt,  g_wt);
    cudaGetSymbolAddress((void**)&pwot, g_wot);
    __nv_bfloat16 *pqh, *pql, *pkh, *pklo, *pvh, *pvlo;
    cudaGetSymbolAddress((void**)&pqh,  g_q2hi);
    cudaGetSymbolAddress((void**)&pql,  g_q2lo);
    cudaGetSymbolAddress((void**)&pkh,  g_k2hi);
    cudaGetSymbolAddress((void**)&pklo, g_k2lo);
    cudaGetSymbolAddress((void**)&pvh,  g_v2hi);
    cudaGetSymbolAddress((void**)&pvlo, g_v2lo);

    static bool attr_done = false;
    if (!attr_done) {
        cudaFuncSetAttribute(gemm_tf32_kernel,
                             cudaFuncAttributeMaxDynamicSharedMemorySize, GEMM_SMEM);
        cudaFuncSetAttribute(attn_mma_kernel,
                             cudaFuncAttributeMaxDynamicSharedMemorySize, ATTN_SMEM);
        attr_done = true;
    }

    // --- prep: tf32-rounded A, transposed+rounded weights ---
    round_tf32_kernel<<<(cM * cHID / 4) / 256, 256>>>(hidden, pahf);
    cvt_wT_kernel<<<dim3(2048 / 32, 2048 / 32), dim3(32, 8)>>>(
        wq, pwt, cHID, 2048);
    cvt_wT_kernel<<<dim3(1024 / 32, 2048 / 32), dim3(32, 8)>>>(
        wk, pwt + (size_t)2048 * cHID, cHID, 1024);
    cvt_wT_kernel<<<dim3(1024 / 32, 2048 / 32), dim3(32, 8)>>>(
        wv, pwt + (size_t)3072 * cHID, cHID, 1024);
    cvt_wT_kernel<<<dim3(2048 / 32, 2048 / 32), dim3(32, 8)>>>(
        wo, pwot, cHID, 2048);

    // --- fused QKV projection (tf32) ---
    gemm_tf32_kernel<<<dim3(cNQKV / GBN, cM / GBM), 256, GEMM_SMEM>>>(
        pahf, pwt, pqkv, cM, cNQKV, cHID);

    // --- RMSNorm + RoPE + bf16 hi/lo split into head-major layout ---
    norm_rope_split_kernel<<<cM * 32, 128>>>(cosp, sinp, qnw, knw);

    // --- single-pass MMA attention + fused weight normalize/zero-fill ---
    attn_mma_kernel<<<dim3(cB * cNKV, cS / 64), 256, ATTN_SMEM>>>(
        pqh, pql, pkh, pklo, pvh, pvlo, weights, pa, write_w);

    // --- output projection (tf32) ---
    gemm_tf32_kernel<<<dim3(cHID / GBN, cM / GBM), 256, GEMM_SMEM>>>(
        pa, pwot, out, cM, cHID, cHID);
}

// round 9
// speedup vs baseline: 1.4149x; 1.0028x over previous
#include <cuda_runtime.h>
#include <cuda_bf16.h>
#include <math.h>
#include <stdint.h>

// ---------------------------------------------------------------------------
// Problem constants
// ---------------------------------------------------------------------------
namespace {
constexpr int cB   = 2;
constexpr int cS   = 2048;
constexpr int cHID = 2048;
constexpr int cNH  = 16;
constexpr int cNKV = 8;
constexpr int cHD  = 128;
constexpr float cEPS   = 1e-6f;
constexpr float cSCALE = 0.08838834764831845f;  // 128^-0.5
constexpr int cM   = cB * cS;        // 4096
constexpr int cNQKV = 4096;          // fused QKV output width
}

// ---------------------------------------------------------------------------
// Scratch (device globals -- no runtime allocation allowed)
// ---------------------------------------------------------------------------
__device__ float g_ahf [(size_t)cM * cHID];        // tf32-rounded hidden
__device__ float g_qkv [(size_t)cM * cNQKV];       // fused QKV projection out
__device__ float g_att [(size_t)cM * cNH * cHD];   // attn out pre-Wo (tf32-rounded)
__device__ float g_wt  [(size_t)cNQKV * cHID];     // [wq|wk|wv]^T tf32-rounded
__device__ float g_wot [(size_t)cHID * cHID];      // wo^T tf32-rounded
__device__ float g_vt  [(size_t)cB * cNKV * cHD * cS]; // V^T fp32 [b][kvh][d][s]

// bf16 hi/lo planes for attention QK, head-major layout [b][h][s][d]
__device__ __nv_bfloat16 g_q2hi[(size_t)cB * cNH  * cS * cHD];
__device__ __nv_bfloat16 g_q2lo[(size_t)cB * cNH  * cS * cHD];
__device__ __nv_bfloat16 g_k2hi[(size_t)cB * cNKV * cS * cHD];
__device__ __nv_bfloat16 g_k2lo[(size_t)cB * cNKV * cS * cHD];

// ---------------------------------------------------------------------------
// PTX helpers (portable: sm_80+)
// ---------------------------------------------------------------------------
__device__ __forceinline__ uint32_t smem_u32(const void* p) {
    uint32_t a;
    asm("{ .reg .u64 t; cvta.to.shared.u64 t, %1; cvt.u32.u64 %0, t; }"
        : "=r"(a) : "l"(p));
    return a;
}
__device__ __forceinline__ void cp_async16(uint32_t saddr, const void* gaddr) {
    asm volatile("cp.async.cg.shared.global [%0], [%1], 16;"
                 :: "r"(saddr), "l"(gaddr) : "memory");
}
#define CP_COMMIT()  asm volatile("cp.async.commit_group;" ::: "memory")
#define CP_WAIT(N)   asm volatile("cp.async.wait_group %0;" :: "n"(N) : "memory")

__device__ __forceinline__ void ldm_x4(uint32_t* r, uint32_t addr) {
    asm volatile("ldmatrix.sync.aligned.m8n8.x4.shared.b16 {%0,%1,%2,%3}, [%4];"
                 : "=r"(r[0]), "=r"(r[1]), "=r"(r[2]), "=r"(r[3]) : "r"(addr));
}
__device__ __forceinline__ void mma16816(float* d, const uint32_t* a,
                                         const uint32_t* b) {
    asm volatile(
        "mma.sync.aligned.m16n8k16.row.col.f32.bf16.bf16.f32 "
        "{%0,%1,%2,%3}, {%4,%5,%6,%7}, {%8,%9}, {%0,%1,%2,%3};"
        : "+f"(d[0]), "+f"(d[1]), "+f"(d[2]), "+f"(d[3])
        : "r"(a[0]), "r"(a[1]), "r"(a[2]), "r"(a[3]), "r"(b[0]), "r"(b[1]));
}
__device__ __forceinline__ void mma1688_tf32(float* d, const uint32_t* a,
                                             const uint32_t* b) {
    asm volatile(
        "mma.sync.aligned.m16n8k8.row.col.f32.tf32.tf32.f32 "
        "{%0,%1,%2,%3}, {%4,%5,%6,%7}, {%8,%9}, {%0,%1,%2,%3};"
        : "+f"(d[0]), "+f"(d[1]), "+f"(d[2]), "+f"(d[3])
        : "r"(a[0]), "r"(a[1]), "r"(a[2]), "r"(a[3]), "r"(b[0]), "r"(b[1]));
}
__device__ __forceinline__ uint32_t sw128(uint32_t off) {
    return off ^ ((off >> 3) & 0x70);
}
__device__ __forceinline__ float tf32r(float x) {
    uint32_t u;
    asm("cvt.rna.tf32.f32 %0, %1;" : "=r"(u) : "f"(x));
    return __uint_as_float(u);
}
__device__ __forceinline__ uint32_t tf32b(float x) {
    uint32_t u;
    asm("cvt.rna.tf32.f32 %0, %1;" : "=r"(u) : "f"(x));
    return u;
}

// ---------------------------------------------------------------------------
// Prep kernels
// ---------------------------------------------------------------------------
__global__ __launch_bounds__(256) void round_tf32_kernel(
    const float* __restrict__ X, float* __restrict__ Y)
{
    size_t e = ((size_t)blockIdx.x * 256 + threadIdx.x) * 4;
    float4 x = *(const float4*)(X + e);
    x.x = tf32r(x.x); x.y = tf32r(x.y); x.z = tf32r(x.z); x.w = tf32r(x.w);
    *(float4*)(Y + e) = x;
}

__global__ __launch_bounds__(256) void cvt_wT_kernel(
    const float* __restrict__ W, float* __restrict__ Y, int K, int N)
{
    __shared__ float t[32][33];
    int n0 = blockIdx.x * 32;
    int k0 = blockIdx.y * 32;
    int tx = threadIdx.x;
    int ty = threadIdx.y;
#pragma unroll
    for (int i = 0; i < 32; i += 8)
        t[ty + i][tx] = W[(size_t)(k0 + ty + i) * N + n0 + tx];
    __syncthreads();
#pragma unroll
    for (int i = 0; i < 32; i += 8) {
        int n = n0 + ty + i;
        int k = k0 + tx;
        Y[(size_t)n * K + k] = tf32r(t[tx][ty + i]);
    }
}

// V^T: g_qkv v-section [b][s][kvh*128+d] -> g_vt [b][kvh][d][s], tf32-rounded
__global__ __launch_bounds__(256) void vT_kernel(
    const float* __restrict__ qkv, float* __restrict__ vt)
{
    __shared__ float t[32][33];
    const int s0 = blockIdx.x * 32;
    const int d0 = blockIdx.y * 32;
    const int bk = blockIdx.z;           // b*8 + kvh
    const int b  = bk >> 3;
    const int kvh = bk & 7;
    const int tx = threadIdx.x;
    const int ty = threadIdx.y;
#pragma unroll
    for (int i = 0; i < 32; i += 8)
        t[ty + i][tx] = qkv[(size_t)(b * cS + s0 + ty + i) * cNQKV +
                            3072 + kvh * cHD + d0 + tx];
    __syncthreads();
#pragma unroll
    for (int i = 0; i < 32; i += 8)
        vt[((size_t)bk * cHD + d0 + ty + i) * cS + s0 + tx] =
            tf32r(t[tx][ty + i]);
}

// ---------------------------------------------------------------------------
// TF32 HMMA GEMM: C[M,N] = A[M,K] @ B[N,K]^T (row-major fp32, tf32-prerounded)
// CTA tile 128x256, BK=32, 4-stage cp.async, SW128, warp tile 64x64.
// ---------------------------------------------------------------------------
namespace {
constexpr int GBM = 128, GBN = 256, GBK = 32;
constexpr int NSTAGE = 4;
constexpr int A_BYTES = GBM * GBK * 4;              // 16KB
constexpr int B_BYTES = GBN * GBK * 4;              // 32KB
constexpr int STAGE_BYTES = A_BYTES + B_BYTES;      // 48KB
constexpr int GEMM_SMEM   = NSTAGE * STAGE_BYTES;   // 192KB
}

__device__ __forceinline__ void gemm_load_stage(
    const float* __restrict__ Ag, const float* __restrict__ Bg,
    int K, int it, uint32_t stage_base, int tid)
{
#pragma unroll
    for (int i = 0; i < 4; i++) {
        int idx = tid + (i << 8);
        int row = idx >> 3;
        int c4  = idx & 7;
        uint32_t sw = sw128((uint32_t)(row * 128 + c4 * 16));
        cp_async16(stage_base + sw,
                   Ag + (size_t)row * K + (size_t)it * GBK + c4 * 4);
    }
#pragma unroll
    for (int i = 0; i < 8; i++) {
        int idx = tid + (i << 8);
        int row = idx >> 3;
        int c4  = idx & 7;
        uint32_t sw = sw128((uint32_t)(row * 128 + c4 * 16));
        cp_async16(stage_base + A_BYTES + sw,
                   Bg + (size_t)row * K + (size_t)it * GBK + c4 * 4);
    }
}

__global__ __launch_bounds__(256, 1)
void gemm_tf32_kernel(const float* __restrict__ A,
                      const float* __restrict__ B,
                      float* __restrict__ C, int M, int N, int K)
{
    extern __shared__ char smraw[];
    const uint32_t sbase = smem_u32(smraw);

    const int tid  = threadIdx.x;
    const int wid  = tid >> 5;
    const int lane = tid & 31;
    const int m0 = blockIdx.y * GBM;
    const int n0 = blockIdx.x * GBN;
    const int mw = (wid >> 2) * 64;
    const int nw = (wid & 3) * 64;

    const float* Ag = A + (size_t)m0 * K;
    const float* Bg = B + (size_t)n0 * K;
    const int KITERS = K / GBK;

    float acc[4][8][4];
#pragma unroll
    for (int i = 0; i < 4; i++)
#pragma unroll
        for (int j = 0; j < 8; j++)
#pragma unroll
            for (int r = 0; r < 4; r++) acc[i][j][r] = 0.f;

    const int a_row = lane & 15;
    const int a_cb  = (lane >> 4) * 16;
    const int b_row = (lane & 7) + ((lane >> 4) & 1) * 8;
    const int b_cb  = ((lane >> 3) & 1) * 16;

#pragma unroll
    for (int s = 0; s < NSTAGE - 1; s++) {
        gemm_load_stage(Ag, Bg, K, s, sbase + s * STAGE_BYTES, tid);
        CP_COMMIT();
    }

    for (int it = 0; it < KITERS; ++it) {
        CP_WAIT(NSTAGE - 2);
        __syncthreads();

        int nx = it + NSTAGE - 1;
        if (nx < KITERS)
            gemm_load_stage(Ag, Bg, K, nx,
                            sbase + (nx % NSTAGE) * STAGE_BYTES, tid);
        CP_COMMIT();

        const uint32_t sa = sbase + (it % NSTAGE) * STAGE_BYTES;
        const uint32_t sb = sa + A_BYTES;

#pragma unroll
        for (int ks = 0; ks < 4; ks++) {
            uint32_t af[4][4], bf[4][4];
#pragma unroll
            for (int mi = 0; mi < 4; mi++) {
                uint32_t off = (uint32_t)((mw + 16 * mi + a_row) * 128 +
                                          ks * 32 + a_cb);
                ldm_x4(af[mi], sa + sw128(off));
            }
#pragma unroll
            for (int njp = 0; njp < 4; njp++) {
                uint32_t off = (uint32_t)((nw + 16 * njp + b_row) * 128 +
                                          ks * 32 + b_cb);
                ldm_x4(bf[njp], sb + sw128(off));
            }
#pragma unroll
            for (int mi = 0; mi < 4; mi++)
#pragma unroll
                for (int njp = 0; njp < 4; njp++) {
                    mma1688_tf32(acc[mi][2 * njp],     af[mi], bf[njp]);
                    mma1688_tf32(acc[mi][2 * njp + 1], af[mi], bf[njp] + 2);
                }
        }
    }

    const int g = lane >> 2;
    const int t = lane & 3;
#pragma unroll
    for (int mi = 0; mi < 4; mi++) {
#pragma unroll
        for (int nj = 0; nj < 8; nj++) {
            int r0 = m0 + mw + 16 * mi + g;
            int cc = n0 + nw + 8 * nj + t * 2;
            *(float2*)(C + (size_t)r0 * N + cc) =
                make_float2(acc[mi][nj][0], acc[mi][nj][1]);
            *(float2*)(C + (size_t)(r0 + 8) * N + cc) =
                make_float2(acc[mi][nj][2], acc[mi][nj][3]);
        }
    }
}

// ---------------------------------------------------------------------------
// RMSNorm + RoPE + hi/lo bf16 split for Q and K only (V handled by vT_kernel).
// Grid: (24, cM); blockIdx.x = slot (0-15 q heads, 16-23 k heads).
// ---------------------------------------------------------------------------
__global__ __launch_bounds__(128) void norm_rope_split_kernel(
    const float* __restrict__ cosp, const float* __restrict__ sinp,
    const float* __restrict__ qw,   const float* __restrict__ kw)
{
    const int slot = blockIdx.x;
    const int bs   = blockIdx.y;
    const int d    = threadIdx.x;
    const int b    = bs >> 11;
    const int s    = bs & 2047;

    const float* src;
    const float* w;
    __nv_bfloat16 *dhi, *dlo;
    if (slot < 16) {
        src = g_qkv + (size_t)bs * cNQKV + slot * cHD;
        w = qw;
        size_t dst = ((size_t)(b * cNH + slot) * cS + s) * cHD;
        dhi = g_q2hi + dst; dlo = g_q2lo + dst;
    } else {
        src = g_qkv + (size_t)bs * cNQKV + 2048 + (slot - 16) * cHD;
        w = kw;
        size_t dst = ((size_t)(b * cNKV + (slot - 16)) * cS + s) * cHD;
        dhi = g_k2hi + dst; dlo = g_k2lo + dst;
    }
    float x = src[d];
    float v = x * x;
#pragma unroll
    for (int o = 16; o; o >>= 1) v += __shfl_xor_sync(0xffffffffu, v, o);
    __shared__ float wsum[4];
    if ((d & 31) == 0) wsum[d >> 5] = v;
    __syncthreads();
    float var = (wsum[0] + wsum[1] + wsum[2] + wsum[3]) * (1.f / cHD);
    float rs  = rsqrtf(var + cEPS);
    float xn  = x * rs * w[d];

    __shared__ float buf[cHD];
    buf[d] = xn;
    __syncthreads();
    float other = (d < cHD / 2) ? -buf[d + cHD / 2] : buf[d - cHD / 2];
    float cv = cosp[(size_t)bs * cHD + d];
    float sv = sinp[(size_t)bs * cHD + d];
    float val = xn * cv + other * sv;

    __nv_bfloat16 hi = __float2bfloat16(val);
    __nv_bfloat16 lo = __float2bfloat16(val - __bfloat162float(hi));
    dhi[d] = hi;
    dlo[d] = lo;
}

// ---------------------------------------------------------------------------
// Single-pass MMA attention: QK bf16 3-term, PV tf32 via K-column-permute
// trick (K smem rows permuted sigma={0,2,4,6,1,3,5,7} within 8-groups so
// QK C-fragments relabel directly into tf32 A-fragments -- no shuffles).
// Fused weight normalize + upper-triangle zero-fill. Heavy-first raster.
// ---------------------------------------------------------------------------
namespace {
constexpr int KTB = 64 * 272;          // K tile bytes (64 rows x 272B)
constexpr int VTB = 128 * 272;         // V^T tile bytes (128 d-rows x 272B)
constexpr int KVSTAGE = 2 * KTB + VTB; // 69632 per stage
constexpr int ATTN_SMEM = 4 * KTB + 2 * KVSTAGE;   // Q(4) + 2 stages = 208896
__device__ __constant__ int c_kperm[8] = {0, 2, 4, 6, 1, 3, 5, 7};
}

__global__ __launch_bounds__(256, 1)
void attn_mma_kernel(const __nv_bfloat16* __restrict__ qhi_g,
                     const __nv_bfloat16* __restrict__ qlo_g,
                     const __nv_bfloat16* __restrict__ khi_g,
                     const __nv_bfloat16* __restrict__ klo_g,
                     const float* __restrict__ vt_g,
                     float* __restrict__ wout,
                     float* __restrict__ outp,
                     int write_w)
{
    extern __shared__ char smraw[];
    const uint32_t uQ  = smem_u32(smraw);
    const uint32_t uKV = uQ + 4 * KTB;

    const int tid  = threadIdx.x;
    const int wid  = tid >> 5;
    const int lane = tid & 31;
    const int qt  = gridDim.y - 1 - blockIdx.y;    // heavy-first
    const int bkv = blockIdx.x;
    const int b   = bkv >> 3;
    const int kvh = bkv & 7;
    const int hs  = wid >> 2;
    const int h   = kvh * 2 + hs;
    const int wr  = (wid & 3) * 16;
    const int q0  = qt * 64;
    const int g   = lane >> 2;
    const int t   = lane & 3;

    // ---- Q tiles (4: h0hi, h0lo, h1hi, h1lo), 64 rows x 256B each
    {
        const size_t qrow = ((size_t)(b * cNH + kvh * 2) * cS + q0) * cHD;
        const int row = (tid >> 4);
        const int c   = tid & 15;
#pragma unroll
        for (int i = 0; i < 16; i++) {
            const int tile = i >> 2;
            const int rr = (i & 3) * 16 + row;
            const __nv_bfloat16* base = (tile & 1) ? qlo_g : qhi_g;
            const __nv_bfloat16* src = base + qrow +
                (size_t)(tile >> 1) * cS * cHD + (size_t)rr * cHD + c * 8;
            cp_async16(uQ + tile * KTB + rr * 272 + c * 16, src);
        }
    }
    CP_COMMIT();

    // ---- KV stage loader (K rows permuted; V^T natural)
    const size_t krow0 = ((size_t)(b * cNKV + kvh) * cS) * cHD;
    const size_t vbase = ((size_t)(b * cNKV + kvh) * cHD) * cS;
    const int lrow = (tid >> 4);
    const int lc   = tid & 15;

#define LOAD_KV_STAGE(kt_, st_)                                               \
    do {                                                                      \
        const uint32_t ust = uKV + (st_) * KVSTAGE;                           \
        const size_t krow = krow0 + (size_t)((kt_) * 64) * cHD;               \
        _Pragma("unroll")                                                     \
        for (int i = 0; i < 8; i++) {                                         \
            const int tile = i >> 2;                                          \
            const int rr = (i & 3) * 16 + lrow;                               \
            const int srr = (rr & 0x38) | c_kperm[rr & 7];                    \
            const __nv_bfloat16* base = tile ? klo_g : khi_g;                 \
            cp_async16(ust + tile * KTB + srr * 272 + lc * 16,                \
                       base + krow + (size_t)rr * cHD + lc * 8);              \
        }                                                                     \
        _Pragma("unroll")                                                     \
        for (int i = 0; i < 8; i++) {                                         \
            const int dd = i * 16 + lrow;                                     \
            cp_async16(ust + 2 * KTB + dd * 272 + lc * 16,                    \
                       vt_g + vbase + (size_t)dd * cS + (kt_) * 64 + lc * 4); \
        }                                                                     \
    } while (0)

    LOAD_KV_STAGE(0, 0);
    CP_COMMIT();

    // ldmatrix per-lane offsets
    const uint32_t qoff = (uint32_t)((wr + (lane & 15)) * 272 + (lane >> 4) * 16);
    const uint32_t koff = (uint32_t)(((lane & 7) + ((lane >> 4) & 1) * 8) * 272 +
                                     ((lane >> 3) & 1) * 16);
    const uint32_t voff = (uint32_t)(((lane & 7) + ((lane >> 4) & 1) * 8) * 272 +
                                     ((lane >> 3) & 1) * 16);
    const uint32_t uQh = uQ + hs * 2 * KTB;
    const uint32_t uQl = uQh + KTB;

    float oacc[16][4];
#pragma unroll
    for (int i = 0; i < 16; i++)
#pragma unroll
        for (int r = 0; r < 4; r++) oacc[i][r] = 0.f;
    float l0 = 0.f, l1 = 0.f;

    for (int kt = 0; kt <= qt; kt++) {
        if (kt < qt) {
            LOAD_KV_STAGE(kt + 1, (kt + 1) & 1);
            CP_COMMIT();
            CP_WAIT(1);
        } else {
            CP_WAIT(0);
        }
        __syncthreads();

        const uint32_t ust  = uKV + (kt & 1) * KVSTAGE;
        const uint32_t ukhi = ust;
        const uint32_t uklo = ust + KTB;
        const uint32_t uvt  = ust + 2 * KTB;

        // ---------- QK: 3-term bf16 hi/lo ----------
        float sacc[8][4];
#pragma unroll
        for (int i = 0; i < 8; i++)
#pragma unroll
            for (int r = 0; r < 4; r++) sacc[i][r] = 0.f;

#pragma unroll
        for (int kk = 0; kk < 8; kk++) {
            uint32_t qh[4], ql[4];
            ldm_x4(qh, uQh + qoff + kk * 32);
            ldm_x4(ql, uQl + qoff + kk * 32);
#pragma unroll
            for (int njp = 0; njp < 4; njp++) {
                uint32_t kb[4];
                ldm_x4(kb, ukhi + njp * (16 * 272) + koff + kk * 32);
                mma16816(sacc[2 * njp],     qh, kb);
                mma16816(sacc[2 * njp + 1], qh, kb + 2);
                mma16816(sacc[2 * njp],     ql, kb);
                mma16816(sacc[2 * njp + 1], ql, kb + 2);
            }
#pragma unroll
            for (int njp = 0; njp < 4; njp++) {
                uint32_t kb[4];
                ldm_x4(kb, uklo + njp * (16 * 272) + koff + kk * 32);
                mma16816(sacc[2 * njp],     qh, kb);
                mma16816(sacc[2 * njp + 1], qh, kb + 2);
            }
        }

        // ---------- exp, mask, sums, weight write, tf32 A-fragments ----------
        // With permuted K: thread (g,t) holds cols (nj*8+t, nj*8+t+4) of rows
        // (wr+g, wr+8+g).
        const bool diag = (kt == qt);
        uint32_t pt[8][4];
#pragma unroll
        for (int nj = 0; nj < 8; nj++) {
            float p0 = __expf(sacc[nj][0] * cSCALE);   // (r0, cb+t)
            float p1 = __expf(sacc[nj][1] * cSCALE);   // (r0, cb+t+4)
            float p2 = __expf(sacc[nj][2] * cSCALE);   // (r1, cb+t)
            float p3 = __expf(sacc[nj][3] * cSCALE);   // (r1, cb+t+4)
            if (diag) {
                const int col0 = nj * 8 + t;
                const int col1 = col0 + 4;
                const int rlo = wr + g, rhi = wr + 8 + g;
                if (col0 > rlo) p0 = 0.f;
                if (col1 > rlo) p1 = 0.f;
                if (col0 > rhi) p2 = 0.f;
                if (col1 > rhi) p3 = 0.f;
            }
            l0 += p0 + p1;
            l1 += p2 + p3;
            if (write_w) {
                float* w0 = wout + ((size_t)(b * cNH + h) * cS + q0 + wr + g) * cS
                            + kt * 64 + nj * 8 + t;
                w0[0] = p0;
                w0[4] = p1;
                float* w1 = w0 + 8 * (size_t)cS;
                w1[0] = p2;
                w1[4] = p3;
            }
            // tf32 A-fragment: {a0,a1,a2,a3} = {(r0,t),(r1,t),(r0,t+4),(r1,t+4)}
            pt[nj][0] = tf32b(p0);
            pt[nj][1] = tf32b(p2);
            pt[nj][2] = tf32b(p1);
            pt[nj][3] = tf32b(p3);
        }

        // ---------- PV: tf32, V^T [d][s] fp32 ----------
#pragma unroll
        for (int nj = 0; nj < 8; nj++) {
#pragma unroll
            for (int nd2 = 0; nd2 < 8; nd2++) {
                uint32_t vb[4];
                ldm_x4(vb, uvt + nd2 * (16 * 272) + nj * 32 + voff);
                mma1688_tf32(oacc[2 * nd2],     pt[nj], vb);
                mma1688_tf32(oacc[2 * nd2 + 1], pt[nj], vb + 2);
            }
        }
        __syncthreads();
    }

    l0 += __shfl_xor_sync(0xffffffffu, l0, 1);
    l0 += __shfl_xor_sync(0xffffffffu, l0, 2);
    l1 += __shfl_xor_sync(0xffffffffu, l1, 1);
    l1 += __shfl_xor_sync(0xffffffffu, l1, 2);
    const float inv0 = 1.f / l0;
    const float inv1 = 1.f / l1;

    // ---- PV output (normalized, tf32-rounded for the Wo GEMM) ----
#pragma unroll
    for (int nd = 0; nd < 16; nd++) {
        const int col = nd * 8 + 2 * t;
        float* o0 = outp + ((size_t)(b * cS + q0 + wr + g) * cNH + h) * cHD + col;
        float* o1 = outp + ((size_t)(b * cS + q0 + wr + 8 + g) * cNH + h) * cHD + col;
        *(float2*)o0 = make_float2(tf32r(oacc[nd][0] * inv0),
                                   tf32r(oacc[nd][1] * inv0));
        *(float2*)o1 = make_float2(tf32r(oacc[nd][2] * inv1),
                                   tf32r(oacc[nd][3] * inv1));
    }

    // ---- fused weight normalization (rescale exactly what this thread wrote)
    if (write_w) {
        const size_t rb0 = ((size_t)(b * cNH + h) * cS + q0 + wr + g) * cS;
        const size_t rb1 = rb0 + 8 * (size_t)cS;
        for (int kt = 0; kt <= qt; kt++) {
#pragma unroll
            for (int nj = 0; nj < 8; nj++) {
                const int cc = kt * 64 + nj * 8 + t;
                float* w0 = wout + rb0 + cc;
                w0[0] *= inv0;
                w0[4] *= inv0;
                float* w1 = wout + rb1 + cc;
                w1[0] *= inv1;
                w1[4] *= inv1;
            }
        }
        // ---- zero the upper-triangle tail of this CTA's 128 rows
        const int zc = cS - (q0 + 64);
        if (zc > 0) {
            const int z4 = zc >> 2;
            const int tot = 128 * z4;
            const float4 z = make_float4(0.f, 0.f, 0.f, 0.f);
            for (int i = tid; i < tot; i += 256) {
                const int r  = i / z4;
                const int c4 = i - r * z4;
                const int head = r >> 6;
                const int row  = r & 63;
                float* p = wout +
                    ((size_t)(b * cNH + kvh * 2 + head) * cS + q0 + row) * cS +
                    q0 + 64 + c4 * 4;
                *(float4*)p = z;
            }
        }
    }
}

// ---------------------------------------------------------------------------
// Launch (single stream)
// ---------------------------------------------------------------------------
extern "C" void kernel_launch(void* const* d_in, const int* in_sizes, int n_in,
                              void* d_out, int out_size)
{
    const float* hidden = (const float*)d_in[0];
    const float* cosp   = (const float*)d_in[1];
    const float* sinp   = (const float*)d_in[2];
    const float* wq  = (const float*)d_in[4];
    const float* wk  = (const float*)d_in[5];
    const float* wv  = (const float*)d_in[6];
    const float* wo  = (const float*)d_in[7];
    const float* qnw = (const float*)d_in[8];
    const float* knw = (const float*)d_in[9];

    float* out = (float*)d_out;
    const size_t n_attn = (size_t)cM * cHID;
    const size_t n_w    = (size_t)cB * cNH * cS * cS;
    const int write_w   = ((size_t)out_size >= n_attn + n_w) ? 1 : 0;
    float* weights = out + n_attn;

    float *pahf, *pqkv, *pa, *pwt, *pwot, *pvt;
    cudaGetSymbolAddress((void**)&pahf, g_ahf);
    cudaGetSymbolAddress((void**)&pqkv, g_qkv);
    cudaGetSymbolAddress((void**)&pa,   g_att);
    cudaGetSymbolAddress((void**)&pwt,  g_wt);
    cudaGetSymbolAddress((void**)&pwot, g_wot);
    cudaGetSymbolAddress((void**)&pvt,  g_vt);
    __nv_bfloat16 *pqh, *pql, *pkh, *pklo;
    cudaGetSymbolAddress((void**)&pqh,  g_q2hi);
    cudaGetSymbolAddress((void**)&pql,  g_q2lo);
    cudaGetSymbolAddress((void**)&pkh,  g_k2hi);
    cudaGetSymbolAddress((void**)&pklo, g_k2lo);

    static bool attr_done = false;
    if (!attr_done) {
        cudaFuncSetAttribute(gemm_tf32_kernel,
                             cudaFuncAttributeMaxDynamicSharedMemorySize, GEMM_SMEM);
        cudaFuncSetAttribute(attn_mma_kernel,
                             cudaFuncAttributeMaxDynamicSharedMemorySize, ATTN_SMEM);
        attr_done = true;
    }

    // --- prep: tf32-rounded A, transposed+rounded weights ---
    round_tf32_kernel<<<(cM * cHID / 4) / 256, 256>>>(hidden, pahf);
    cvt_wT_kernel<<<dim3(2048 / 32, 2048 / 32), dim3(32, 8)>>>(
        wq, pwt, cHID, 2048);
    cvt_wT_kernel<<<dim3(1024 / 32, 2048 / 32), dim3(32, 8)>>>(
        wk, pwt + (size_t)2048 * cHID, cHID, 1024);
    cvt_wT_kernel<<<dim3(1024 / 32, 2048 / 32), dim3(32, 8)>>>(
        wv, pwt + (size_t)3072 * cHID, cHID, 1024);
    cvt_wT_kernel<<<dim3(2048 / 32, 2048 / 32), dim3(32, 8)>>>(
        wo, pwot, cHID, 2048);

    // --- fused QKV projection (tf32) ---
    gemm_tf32_kernel<<<dim3(cNQKV / GBN, cM / GBM), 256, GEMM_SMEM>>>(
        pahf, pwt, pqkv, cM, cNQKV, cHID);

    // --- RMSNorm + RoPE + bf16 hi/lo split (Q,K); V^T transpose (tf32) ---
    norm_rope_split_kernel<<<dim3(24, cM), 128>>>(cosp, sinp, qnw, knw);
    vT_kernel<<<dim3(cS / 32, cHD / 32, cB * cNKV), dim3(32, 8)>>>(pqkv, pvt);

    // --- single-pass MMA attention + fused weight normalize/zero-fill ---
    attn_mma_kernel<<<dim3(cB * cNKV, cS / 64), 256, ATTN_SMEM>>>(
        pqh, pql, pkh, pklo, pvt, weights, pa, write_w);

    // --- output projection (tf32) ---
    gemm_tf32_kernel<<<dim3(cHID / GBN, cM / GBM), 256, GEMM_SMEM>>>(
        pa, pwot, out, cM, cHID, cHID);
}